// round 17
// baseline (speedup 1.0000x reference)
#include <cuda_runtime.h>
#include <cuda_bf16.h>
#include <math.h>
#include <stdint.h>

#define B     128
#define H     2048
#define E     64
#define I     768
#define TWO_I 1536
#define TOPK  8

// -------- device-global scratch (no allocations allowed) --------
__device__ float g_routing[B * E];
__device__ int   g_count[E];
__device__ int   g_tokens[E * B];
__device__ float g_inter[(size_t)E * B * I];     // silu(g)*u (~25 MB)

// ======================= helpers =======================
__device__ __forceinline__ void mma_bf16(float* d, const uint32_t* a, const uint32_t* b) {
    asm volatile("mma.sync.aligned.m16n8k16.row.col.f32.bf16.bf16.f32 "
        "{%0,%1,%2,%3}, {%4,%5,%6,%7}, {%8,%9}, {%0,%1,%2,%3};"
        : "+f"(d[0]), "+f"(d[1]), "+f"(d[2]), "+f"(d[3])
        : "r"(a[0]), "r"(a[1]), "r"(a[2]), "r"(a[3]), "r"(b[0]), "r"(b[1]));
}
// split fp32 pair -> hi/lo bf16x2 words (low half = first element = lower k)
__device__ __forceinline__ void split2(float2 v, uint32_t& h, uint32_t& l) {
    asm("cvt.rn.bf16x2.f32 %0, %1, %2;" : "=r"(h) : "f"(v.y), "f"(v.x));
    float r0 = v.x - __uint_as_float(h << 16);
    float r1 = v.y - __uint_as_float(h & 0xffff0000u);
    asm("cvt.rn.bf16x2.f32 %0, %1, %2;" : "=r"(l) : "f"(r1), "f"(r0));
}

// ============================================================================
// Kernel 0: zero output + counters
// ============================================================================
__global__ void k_zero(float* __restrict__ out) {
    int idx = blockIdx.x * blockDim.x + threadIdx.x;
    if (idx < B * H) out[idx] = 0.f;
    if (idx < E) g_count[idx] = 0;
}

// ============================================================================
// Kernel 1: routing (proven)
// ============================================================================
__global__ void k_route(const float* __restrict__ x, const float* __restrict__ gw) {
    int b = blockIdx.x, tid = threadIdx.x, warp = tid >> 5, lane = tid & 31;
    __shared__ float sl[E];
    const float4* xr = (const float4*)(x + (size_t)b * H);
    for (int j = 0; j < 8; ++j) {
        int e = warp * 8 + j;
        const float4* gr = (const float4*)(gw + (size_t)e * H);
        float acc = 0.f;
        for (int t = lane; t < H / 4; t += 32) {
            float4 xv = xr[t], gv = gr[t];
            acc += xv.x * gv.x + xv.y * gv.y + xv.z * gv.z + xv.w * gv.w;
        }
        #pragma unroll
        for (int o = 16; o > 0; o >>= 1) acc += __shfl_xor_sync(0xffffffffu, acc, o);
        if (lane == 0) sl[e] = acc;
    }
    __syncthreads();
    if (tid == 0) {
        float m = sl[0];
        #pragma unroll
        for (int e = 1; e < E; ++e) m = fmaxf(m, sl[e]);
        float p[E];
        #pragma unroll
        for (int e = 0; e < E; ++e) p[e] = expf(sl[e] - m);
        int sel[TOPK]; float val[TOPK]; float ssum = 0.f;
        for (int k = 0; k < TOPK; ++k) {
            int best = 0; float bv = -1.f;
            for (int e = 0; e < E; ++e) if (p[e] > bv) { bv = p[e]; best = e; }
            sel[k] = best; val[k] = bv; ssum += bv; p[best] = -2.f;
        }
        for (int k = 0; k < TOPK; ++k) {
            int e = sel[k];
            g_routing[b * E + e] = val[k] / ssum;
            int pos = atomicAdd(&g_count[e], 1);
            g_tokens[e * B + pos] = b;
        }
    }
}

// ============================================================================
// Direct-fragment HMMA grouped GEMM, phase A (fused silu). NO smem mainloop:
// each lane LDGs its own mma fragment elements (float2, 4 lanes = 32B runs),
// hi/lo bf16 split in registers, 3-pass MMA. No barriers in the K loop.
// Block: 128 thr = 4 warps; warp owns 32 rows. Rows 0..63 = gate, 64..127 = up.
// Grid (I/64=12, E, 4).
// ============================================================================
__global__ void __launch_bounds__(128)
k_mma_up(const float* __restrict__ x, const float* __restrict__ w1) {
    int e = blockIdx.y, cnt = g_count[e];
    int m0 = blockIdx.z * 32;
    if (m0 >= cnt) return;
    int n0g = blockIdx.x * 64;
    int tid = threadIdx.x, wid = tid >> 5, lid = tid & 31;
    int g = lid >> 2, t = lid & 3;

    __shared__ float C[128][33];
    __shared__ int toks[32];
    if (tid < 32) toks[tid] = (m0 + tid < cnt) ? g_tokens[e * B + m0 + tid] : -1;
    __syncthreads();

    // A base pointer: warp's first fragment row (row rr, k offset 2t).
    // Warp covers rows rr + {0,8,16,24}; wid 0,1 -> gate rows, wid 2,3 -> up rows.
    int rr = wid * 32 + g;
    const float* Abase;
    if (rr < 64) Abase = w1 + ((size_t)e * TWO_I + n0g + rr) * H + 2 * t;
    else         Abase = w1 + ((size_t)e * TWO_I + I + n0g + (rr - 64)) * H + 2 * t;

    // B pointers: token nt*8+g, k offset 2t
    const float* Bp[4]; bool bv[4];
    #pragma unroll
    for (int nt = 0; nt < 4; ++nt) {
        int tk = toks[nt * 8 + g];
        bv[nt] = (tk >= 0);
        Bp[nt] = x + (size_t)(tk >= 0 ? tk : 0) * H + 2 * t;
    }

    float acc[2][4][4];
    #pragma unroll
    for (int i = 0; i < 2; ++i)
        #pragma unroll
        for (int j = 0; j < 4; ++j)
            #pragma unroll
            for (int r = 0; r < 4; ++r) acc[i][j][r] = 0.f;

    const float2 z2 = make_float2(0.f, 0.f);

    // prefetch A fragments for kk=0
    float2 an[2][4];
    #pragma unroll
    for (int mt = 0; mt < 2; ++mt) {
        const float* p = Abase + (size_t)(mt * 16) * H;
        an[mt][0] = *(const float2*)(p);
        an[mt][1] = *(const float2*)(p + 8 * H);
        an[mt][2] = *(const float2*)(p + 8);
        an[mt][3] = *(const float2*)(p + 8 * H + 8);
    }

    #pragma unroll 2
    for (int kk = 0; kk < H; kk += 16) {
        float2 a[2][4];
        #pragma unroll
        for (int mt = 0; mt < 2; ++mt)
            #pragma unroll
            for (int r = 0; r < 4; ++r) a[mt][r] = an[mt][r];

        if (kk + 16 < H) {      // prefetch next (overlaps split+mma via scoreboard)
            #pragma unroll
            for (int mt = 0; mt < 2; ++mt) {
                const float* p = Abase + (size_t)(mt * 16) * H + kk + 16;
                an[mt][0] = *(const float2*)(p);
                an[mt][1] = *(const float2*)(p + 8 * H);
                an[mt][2] = *(const float2*)(p + 8);
                an[mt][3] = *(const float2*)(p + 8 * H + 8);
            }
        }

        // B loads (L1-hot: shared by all 4 warps)
        float2 b[4][2];
        #pragma unroll
        for (int nt = 0; nt < 4; ++nt) {
            b[nt][0] = bv[nt] ? *(const float2*)(Bp[nt] + kk)     : z2;
            b[nt][1] = bv[nt] ? *(const float2*)(Bp[nt] + kk + 8) : z2;
        }

        uint32_t ah[2][4], al[2][4], bh[4][2], bl[4][2];
        #pragma unroll
        for (int mt = 0; mt < 2; ++mt)
            #pragma unroll
            for (int r = 0; r < 4; ++r) split2(a[mt][r], ah[mt][r], al[mt][r]);
        #pragma unroll
        for (int nt = 0; nt < 4; ++nt) {
            split2(b[nt][0], bh[nt][0], bl[nt][0]);
            split2(b[nt][1], bh[nt][1], bl[nt][1]);
        }

        #pragma unroll
        for (int mt = 0; mt < 2; ++mt)
            #pragma unroll
            for (int nt = 0; nt < 4; ++nt) {
                mma_bf16(acc[mt][nt], ah[mt], bh[nt]);   // hi*hi
                mma_bf16(acc[mt][nt], ah[mt], bl[nt]);   // hi*lo
                mma_bf16(acc[mt][nt], al[mt], bh[nt]);   // lo*hi
            }
    }

    // epilogue: stage to C, silu(gate)*up -> g_inter coalesced (same as R14)
    int l4 = lid >> 2, l2 = (lid & 3) * 2;
    #pragma unroll
    for (int mt = 0; mt < 2; ++mt)
        #pragma unroll
        for (int nt = 0; nt < 4; ++nt)
            #pragma unroll
            for (int r = 0; r < 4; ++r) {
                int row = wid * 32 + mt * 16 + l4 + (r >> 1) * 8;
                int col = nt * 8 + l2 + (r & 1);
                C[row][col] = acc[mt][nt][r];
            }
    __syncthreads();

    int vcols = min(32, cnt - m0);
    #pragma unroll
    for (int it = 0; it < 16; ++it) {
        int idx = tid + it * 128;
        int col = idx >> 6;          // slot 0..31
        int row = idx & 63;          // i offset 0..63
        if (col < vcols) {
            float gg = C[row][col];
            float uu = C[row + 64][col];
            g_inter[((size_t)e * B + m0 + col) * I + n0g + row] =
                (gg / (1.f + expf(-gg))) * uu;
        }
    }
}

// ============================================================================
// Direct-fragment HMMA grouped GEMM, phase B: out += rw * (w2[e] @ inter^T)
// Same scheme. Grid (H/128=16, E, 4). K = I = 768.
// ============================================================================
__global__ void __launch_bounds__(128)
k_mma_down(const float* __restrict__ w2, float* __restrict__ out) {
    int e = blockIdx.y, cnt = g_count[e];
    int m0 = blockIdx.z * 32;
    if (m0 >= cnt) return;
    int n0 = blockIdx.x * 128;
    int tid = threadIdx.x, wid = tid >> 5, lid = tid & 31;
    int g = lid >> 2, t = lid & 3;

    __shared__ int   toks[32];
    __shared__ float rw[32];
    if (tid < 32) {
        int tk = (m0 + tid < cnt) ? g_tokens[e * B + m0 + tid] : -1;
        toks[tid] = tk;
        rw[tid]   = (tk >= 0) ? g_routing[tk * E + e] : 0.f;
    }
    __syncthreads();

    const float* Abase = w2 + (size_t)e * H * I + (size_t)(n0 + wid * 32 + g) * I + 2 * t;

    const float* Bp[4]; bool bv[4];
    #pragma unroll
    for (int nt = 0; nt < 4; ++nt) {
        int slot = m0 + nt * 8 + g;
        bv[nt] = (slot < cnt);
        Bp[nt] = g_inter + ((size_t)e * B + (slot < cnt ? slot : 0)) * I + 2 * t;
    }

    float acc[2][4][4];
    #pragma unroll
    for (int i = 0; i < 2; ++i)
        #pragma unroll
        for (int j = 0; j < 4; ++j)
            #pragma unroll
            for (int r = 0; r < 4; ++r) acc[i][j][r] = 0.f;

    const float2 z2 = make_float2(0.f, 0.f);

    float2 an[2][4];
    #pragma unroll
    for (int mt = 0; mt < 2; ++mt) {
        const float* p = Abase + (size_t)(mt * 16) * I;
        an[mt][0] = *(const float2*)(p);
        an[mt][1] = *(const float2*)(p + 8 * I);
        an[mt][2] = *(const float2*)(p + 8);
        an[mt][3] = *(const float2*)(p + 8 * I + 8);
    }

    #pragma unroll 2
    for (int kk = 0; kk < I; kk += 16) {
        float2 a[2][4];
        #pragma unroll
        for (int mt = 0; mt < 2; ++mt)
            #pragma unroll
            for (int r = 0; r < 4; ++r) a[mt][r] = an[mt][r];

        if (kk + 16 < I) {
            #pragma unroll
            for (int mt = 0; mt < 2; ++mt) {
                const float* p = Abase + (size_t)(mt * 16) * I + kk + 16;
                an[mt][0] = *(const float2*)(p);
                an[mt][1] = *(const float2*)(p + 8 * I);
                an[mt][2] = *(const float2*)(p + 8);
                an[mt][3] = *(const float2*)(p + 8 * I + 8);
            }
        }

        float2 b[4][2];
        #pragma unroll
        for (int nt = 0; nt < 4; ++nt) {
            b[nt][0] = bv[nt] ? *(const float2*)(Bp[nt] + kk)     : z2;
            b[nt][1] = bv[nt] ? *(const float2*)(Bp[nt] + kk + 8) : z2;
        }

        uint32_t ah[2][4], al[2][4], bh[4][2], bl[4][2];
        #pragma unroll
        for (int mt = 0; mt < 2; ++mt)
            #pragma unroll
            for (int r = 0; r < 4; ++r) split2(a[mt][r], ah[mt][r], al[mt][r]);
        #pragma unroll
        for (int nt = 0; nt < 4; ++nt) {
            split2(b[nt][0], bh[nt][0], bl[nt][0]);
            split2(b[nt][1], bh[nt][1], bl[nt][1]);
        }

        #pragma unroll
        for (int mt = 0; mt < 2; ++mt)
            #pragma unroll
            for (int nt = 0; nt < 4; ++nt) {
                mma_bf16(acc[mt][nt], ah[mt], bh[nt]);
                mma_bf16(acc[mt][nt], ah[mt], bl[nt]);
                mma_bf16(acc[mt][nt], al[mt], bh[nt]);
            }
    }

    int l4 = lid >> 2, l2 = (lid & 3) * 2;
    #pragma unroll
    for (int mt = 0; mt < 2; ++mt)
        #pragma unroll
        for (int nt = 0; nt < 4; ++nt)
            #pragma unroll
            for (int r = 0; r < 4; ++r) {
                int col = nt * 8 + l2 + (r & 1);
                int tk  = toks[col];
                if (tk >= 0) {
                    int row = wid * 32 + mt * 16 + l4 + (r >> 1) * 8;
                    atomicAdd(out + (size_t)tk * H + n0 + row, rw[col] * acc[mt][nt][r]);
                }
            }
}

// ============================================================================
// Launch
// ============================================================================
extern "C" void kernel_launch(void* const* d_in, const int* in_sizes, int n_in,
                              void* d_out, int out_size) {
    const float* x  = (const float*)d_in[0];   // (128, 2048)
    const float* gw = (const float*)d_in[1];   // (64, 2048)
    const float* w1 = (const float*)d_in[2];   // (64, 1536, 2048)
    const float* w2 = (const float*)d_in[3];   // (64, 2048, 768)
    float* out = (float*)d_out;                // (128, 1, 2048)

    k_zero<<<(B * H + 255) / 256, 256>>>(out);
    k_route<<<B, 256>>>(x, gw);

    dim3 gA(I / 64, E, B / 32);        // (12, 64, 4)
    k_mma_up<<<gA, 128>>>(x, w1);

    dim3 gB(H / 128, E, B / 32);       // (16, 64, 4)
    k_mma_down<<<gB, 128>>>(w2, out);
}